// round 6
// baseline (speedup 1.0000x reference)
#include <cuda_runtime.h>
#include <cuda_fp16.h>
#include <math.h>
#include <stdint.h>

#define NLV   16
#define TBITS 19
#define TSZ   (1u << TBITS)
#define BLOCK 256
#define PPB   128   // points per block (2 threads encode each point)

typedef unsigned int u32;

struct LvlParams {
    float scale[NLV];
    int   res[NLV];
    int   dense[NLV];
};

// softplus(10z)/10 = max(z,0) + (ln2/10) * lg2(1 + 2^(-10*log2(e)*|z|))
__device__ __forceinline__ float softplus10(float z) {
    float e, l;
    float a = -14.426950408889634f * fabsf(z);
    asm("ex2.approx.ftz.f32 %0, %1;" : "=f"(e) : "f"(a));
    float p = 1.0f + e;
    asm("lg2.approx.ftz.f32 %0, %1;" : "=f"(l) : "f"(p));
    return fmaf(l, 0.069314718055994531f, fmaxf(z, 0.0f));
}

// pack two f32 -> f16x2; first operand lands in HIGH half
__device__ __forceinline__ u32 f22h2(float hi, float lo) {
    u32 r;
    asm("cvt.rn.f16x2.f32 %0, %1, %2;" : "=r"(r) : "f"(hi), "f"(lo));
    return r;
}

__device__ __forceinline__ void ldsm4(u32& r0, u32& r1, u32& r2, u32& r3, u32 addr) {
    asm volatile("ldmatrix.sync.aligned.m8n8.x4.shared.b16 {%0,%1,%2,%3}, [%4];"
        : "=r"(r0), "=r"(r1), "=r"(r2), "=r"(r3) : "r"(addr));
}

__device__ __forceinline__ void mma16816(float* d, const u32* a, u32 b0, u32 b1) {
    asm volatile("mma.sync.aligned.m16n8k16.row.col.f32.f16.f16.f32 "
        "{%0,%1,%2,%3},{%4,%5,%6,%7},{%8,%9},{%0,%1,%2,%3};"
        : "+f"(d[0]), "+f"(d[1]), "+f"(d[2]), "+f"(d[3])
        : "r"(a[0]), "r"(a[1]), "r"(a[2]), "r"(a[3]), "r"(b0), "r"(b1));
}

__device__ __forceinline__ void level_setup(float px, float py, float pz,
                                            float sc, int res, bool dens,
                                            u32 idx[8], float w[3])
{
    float fx = px * sc + 0.5f, fy = py * sc + 0.5f, fz = pz * sc + 0.5f;
    float gx = floorf(fx), gy = floorf(fy), gz = floorf(fz);
    w[0] = fx - gx; w[1] = fy - gy; w[2] = fz - gz;
    int cx = (int)gx, cy = (int)gy, cz = (int)gz;

    u32 tx[2], ty[2], tz[2];
    if (dens) {
        tx[0] = (u32)min(max(cx,     0), res - 1);
        tx[1] = (u32)min(max(cx + 1, 0), res - 1);
        ty[0] = (u32)(min(max(cy,     0), res - 1) * res);
        ty[1] = (u32)(min(max(cy + 1, 0), res - 1) * res);
        tz[0] = (u32)(min(max(cz,     0), res - 1) * (res * res));
        tz[1] = (u32)(min(max(cz + 1, 0), res - 1) * (res * res));
        #pragma unroll
        for (int c = 0; c < 8; c++)
            idx[c] = tx[(c >> 2) & 1] + ty[(c >> 1) & 1] + tz[c & 1];
    } else {
        u32 ux = (u32)cx, uy = (u32)cy, uz = (u32)cz;
        tx[0] = ux;               tx[1] = ux + 1u;
        ty[0] = uy * 2654435761u; ty[1] = ty[0] + 2654435761u;
        tz[0] = uz * 805459861u;  tz[1] = tz[0] + 805459861u;
        #pragma unroll
        for (int c = 0; c < 8; c++)
            idx[c] = (tx[(c >> 2) & 1] ^ ty[(c >> 1) & 1] ^ tz[c & 1]) & (TSZ - 1u);
    }
}

__device__ __forceinline__ u32 level_reduce(const float2 f[8], const float w[3]) {
    const float wx = w[0], wy = w[1], wz = w[2];
    const float wx0 = 1.f - wx, wy0 = 1.f - wy, wz0 = 1.f - wz;
    float f0 = 0.f, f1 = 0.f;
    #pragma unroll
    for (int c = 0; c < 8; c++) {
        const int ox = (c >> 2) & 1, oy = (c >> 1) & 1, oz = c & 1;
        float wc = (ox ? wx : wx0) * (oy ? wy : wy0) * (oz ? wz : wz0);
        f0 = fmaf(wc, f[c].x, f0);
        f1 = fmaf(wc, f[c].y, f1);
    }
    return f22h2(f1, f0);
}

__global__ void __launch_bounds__(BLOCK, 3)
sdf_kernel(const float* __restrict__ x,
           const float* __restrict__ table,
           const float* __restrict__ w1,
           const float* __restrict__ w2,
           const float* __restrict__ w3,
           const float* __restrict__ w4,
           float* __restrict__ out,
           int n, LvlParams P)
{
    __shared__ __align__(16) __half s_w1[64 * 40];
    __shared__ __align__(16) __half s_w2[64 * 72];
    __shared__ __align__(16) __half s_w3[64 * 72];
    __shared__ float s_w4[64];
    __shared__ __align__(16) __half s_enc[PPB * 40]; // 128 rows, stride 40 halves (80B)

    const int tid  = threadIdx.x;
    const int lane = tid & 31;
    const int warp = tid >> 5;

    // ---- prologue: convert weights to fp16 smem ----
    for (int t = tid; t < 64 * 32; t += BLOCK) {
        int nn = t >> 5, kk = t & 31;
        s_w1[nn * 40 + kk] = __float2half_rn(w1[t]);
    }
    for (int t = tid; t < 64 * 64; t += BLOCK) {
        int nn = t >> 6, kk = t & 63;
        s_w2[nn * 72 + kk] = __float2half_rn(w2[t]);
        s_w3[nn * 72 + kk] = __float2half_rn(w3[t]);
    }
    if (tid < 64) s_w4[tid] = w4[tid];
    __syncthreads();

    // ---- encode: 2 threads per point, 8 levels each, level-pair batching ----
    const int pt  = tid >> 1;                      // block-local point 0..127
    const int i   = blockIdx.x * PPB + pt;
    const int ic  = (i < n) ? i : (n - 1);
    const int lh  = (tid & 1) * 8;                 // this thread's level range [lh, lh+8)

    const float px = x[3 * ic + 0];
    const float py = x[3 * ic + 1];
    const float pz = x[3 * ic + 2];

    u32* encw = reinterpret_cast<u32*>(s_enc);

    #pragma unroll 1
    for (int lp = 0; lp < 4; lp++) {
        const int lA = lh + 2 * lp, lB = lA + 1;
        u32 idxA[8], idxB[8];
        float wA[3], wB[3];
        level_setup(px, py, pz, P.scale[lA], P.res[lA], P.dense[lA] != 0, idxA, wA);
        level_setup(px, py, pz, P.scale[lB], P.res[lB], P.dense[lB] != 0, idxB, wB);

        const float2* tA = reinterpret_cast<const float2*>(table) + (size_t)lA * TSZ;
        const float2* tB = reinterpret_cast<const float2*>(table) + (size_t)lB * TSZ;

        float2 fA[8], fB[8];
        #pragma unroll
        for (int c = 0; c < 8; c++) fA[c] = __ldg(&tA[idxA[c]]);
        #pragma unroll
        for (int c = 0; c < 8; c++) fB[c] = __ldg(&tB[idxB[c]]);

        encw[pt * 20 + lA] = level_reduce(fA, wA);
        encw[pt * 20 + lB] = level_reduce(fB, wB);
    }
    __syncwarp();  // rows [warp*16, warp*16+16) written by this warp's threads only

    // ---- MLP on tensor cores: warp owns 16 points (one m-tile) ----
    const u32 enc_b = (u32)__cvta_generic_to_shared(s_enc);
    const u32 w1_b  = (u32)__cvta_generic_to_shared(s_w1);
    const u32 w2_b  = (u32)__cvta_generic_to_shared(s_w2);
    const u32 w3_b  = (u32)__cvta_generic_to_shared(s_w3);

    float d[8][4];
    u32   a[4][4];

    // layer 1: 32 -> 64
    #pragma unroll
    for (int kt = 0; kt < 2; kt++) {
        u32 addr = enc_b + (u32)((warp * 16 + (lane & 15)) * 80
                                 + kt * 32 + (lane >> 4) * 16);
        ldsm4(a[kt][0], a[kt][1], a[kt][2], a[kt][3], addr);
    }
    #pragma unroll
    for (int nt = 0; nt < 8; nt++)
        #pragma unroll
        for (int v = 0; v < 4; v++) d[nt][v] = 0.f;

    #pragma unroll
    for (int kt = 0; kt < 2; kt++)
        #pragma unroll
        for (int u = 0; u < 4; u++) {
            u32 b0, b1, b2, b3;
            u32 addr = w1_b + (u32)((u * 16 + (lane >> 4) * 8 + (lane & 7)) * 80
                                    + kt * 32 + ((lane >> 3) & 1) * 16);
            ldsm4(b0, b1, b2, b3, addr);
            mma16816(d[2 * u],     a[kt], b0, b1);
            mma16816(d[2 * u + 1], a[kt], b2, b3);
        }

    #pragma unroll
    for (int kk = 0; kk < 4; kk++) {
        a[kk][0] = f22h2(softplus10(d[2*kk][1]),   softplus10(d[2*kk][0]));
        a[kk][1] = f22h2(softplus10(d[2*kk][3]),   softplus10(d[2*kk][2]));
        a[kk][2] = f22h2(softplus10(d[2*kk+1][1]), softplus10(d[2*kk+1][0]));
        a[kk][3] = f22h2(softplus10(d[2*kk+1][3]), softplus10(d[2*kk+1][2]));
    }

    // layers 2 and 3: 64 -> 64
    #pragma unroll 1
    for (int layer = 0; layer < 2; layer++) {
        const u32 wb = (layer == 0) ? w2_b : w3_b;
        #pragma unroll
        for (int nt = 0; nt < 8; nt++)
            #pragma unroll
            for (int v = 0; v < 4; v++) d[nt][v] = 0.f;

        #pragma unroll
        for (int kt = 0; kt < 4; kt++)
            #pragma unroll
            for (int u = 0; u < 4; u++) {
                u32 b0, b1, b2, b3;
                u32 addr = wb + (u32)((u * 16 + (lane >> 4) * 8 + (lane & 7)) * 144
                                      + kt * 32 + ((lane >> 3) & 1) * 16);
                ldsm4(b0, b1, b2, b3, addr);
                mma16816(d[2 * u],     a[kt], b0, b1);
                mma16816(d[2 * u + 1], a[kt], b2, b3);
            }

        if (layer == 0) {
            #pragma unroll
            for (int kk = 0; kk < 4; kk++) {
                a[kk][0] = f22h2(softplus10(d[2*kk][1]),   softplus10(d[2*kk][0]));
                a[kk][1] = f22h2(softplus10(d[2*kk][3]),   softplus10(d[2*kk][2]));
                a[kk][2] = f22h2(softplus10(d[2*kk+1][1]), softplus10(d[2*kk+1][0]));
                a[kk][3] = f22h2(softplus10(d[2*kk+1][3]), softplus10(d[2*kk+1][2]));
            }
        }
    }

    // layer 4: 64 -> 1
    {
        float p0 = 0.f, p1 = 0.f;
        #pragma unroll
        for (int nt = 0; nt < 8; nt++) {
            int c = nt * 8 + 2 * (lane & 3);
            float wv0 = s_w4[c], wv1 = s_w4[c + 1];
            p0 = fmaf(softplus10(d[nt][0]), wv0, p0);
            p0 = fmaf(softplus10(d[nt][1]), wv1, p0);
            p1 = fmaf(softplus10(d[nt][2]), wv0, p1);
            p1 = fmaf(softplus10(d[nt][3]), wv1, p1);
        }
        p0 += __shfl_xor_sync(0xffffffffu, p0, 1);
        p0 += __shfl_xor_sync(0xffffffffu, p0, 2);
        p1 += __shfl_xor_sync(0xffffffffu, p1, 1);
        p1 += __shfl_xor_sync(0xffffffffu, p1, 2);
        if ((lane & 3) == 0) {
            int r0 = blockIdx.x * PPB + warp * 16 + (lane >> 2);
            if (r0 < n) out[r0] = p0;
            int r1 = r0 + 8;
            if (r1 < n) out[r1] = p1;
        }
    }
}

extern "C" void kernel_launch(void* const* d_in, const int* in_sizes, int n_in,
                              void* d_out, int out_size)
{
    const float* x     = (const float*)d_in[0];
    const float* table = (const float*)d_in[1];
    const float* w1    = (const float*)d_in[2];
    const float* w2    = (const float*)d_in[3];
    const float* w3    = (const float*)d_in[4];
    const float* w4    = (const float*)d_in[5];
    float* out = (float*)d_out;

    const int n = in_sizes[0] / 3;

    LvlParams P;
    const double pls = exp2(7.0 / 15.0);
    const double l2s = log2(pls);
    for (int l = 0; l < NLV; l++) {
        double s = exp2((double)l * l2s) * 16.0 - 1.0;
        P.scale[l] = (float)s;
        long long r = (long long)ceil(s) + 1;
        P.res[l] = (int)r;
        P.dense[l] = (r * r * r <= (long long)TSZ) ? 1 : 0;
    }

    int grid = (n + PPB - 1) / PPB;
    sdf_kernel<<<grid, BLOCK>>>(x, table, w1, w2, w3, w4, out, n, P);
}

// round 7
// speedup vs baseline: 1.0980x; 1.0980x over previous
#include <cuda_runtime.h>
#include <cuda_fp16.h>
#include <math.h>
#include <stdint.h>

#define NLV   16
#define TBITS 19
#define TSZ   (1u << TBITS)
#define BLOCK 256

typedef unsigned int u32;

struct LvlParams {
    float scale[NLV];
    int   res[NLV];
    int   dense[NLV];
};

// softplus(10z)/10 = max(z,0) + (ln2/10) * lg2(1 + 2^(-10*log2(e)*|z|))
__device__ __forceinline__ float softplus10(float z) {
    float e, l;
    float a = -14.426950408889634f * fabsf(z);
    asm("ex2.approx.ftz.f32 %0, %1;" : "=f"(e) : "f"(a));
    float p = 1.0f + e;
    asm("lg2.approx.ftz.f32 %0, %1;" : "=f"(l) : "f"(p));
    return fmaf(l, 0.069314718055994531f, fmaxf(z, 0.0f));
}

// pack two f32 -> f16x2; first operand lands in HIGH half
__device__ __forceinline__ u32 f22h2(float hi, float lo) {
    u32 r;
    asm("cvt.rn.f16x2.f32 %0, %1, %2;" : "=r"(r) : "f"(hi), "f"(lo));
    return r;
}

__device__ __forceinline__ void ldsm4(u32& r0, u32& r1, u32& r2, u32& r3, u32 addr) {
    asm volatile("ldmatrix.sync.aligned.m8n8.x4.shared.b16 {%0,%1,%2,%3}, [%4];"
        : "=r"(r0), "=r"(r1), "=r"(r2), "=r"(r3) : "r"(addr));
}

__device__ __forceinline__ void mma16816(float* d, const u32* a, u32 b0, u32 b1) {
    asm volatile("mma.sync.aligned.m16n8k16.row.col.f32.f16.f16.f32 "
        "{%0,%1,%2,%3},{%4,%5,%6,%7},{%8,%9},{%0,%1,%2,%3};"
        : "+f"(d[0]), "+f"(d[1]), "+f"(d[2]), "+f"(d[3])
        : "r"(a[0]), "r"(a[1]), "r"(a[2]), "r"(a[3]), "r"(b0), "r"(b1));
}

// Per level: 4 x-corner index pairs (i0 = corner ox=0, i1 = corner ox=1) for
// the 4 (oy,oz) combos, plus interp weights.
__device__ __forceinline__ void pair_setup(float px, float py, float pz,
                                           float sc, int res, bool dens,
                                           u32 i0[4], u32 i1[4], float w[3])
{
    float fx = px * sc + 0.5f, fy = py * sc + 0.5f, fz = pz * sc + 0.5f;
    float gx = floorf(fx), gy = floorf(fy), gz = floorf(fz);
    w[0] = fx - gx; w[1] = fy - gy; w[2] = fz - gz;
    int cx = (int)gx, cy = (int)gy, cz = (int)gz;

    u32 tx[2], ty[2], tz[2];
    if (dens) {
        tx[0] = (u32)min(max(cx,     0), res - 1);
        tx[1] = (u32)min(max(cx + 1, 0), res - 1);
        ty[0] = (u32)(min(max(cy,     0), res - 1) * res);
        ty[1] = (u32)(min(max(cy + 1, 0), res - 1) * res);
        tz[0] = (u32)(min(max(cz,     0), res - 1) * (res * res));
        tz[1] = (u32)(min(max(cz + 1, 0), res - 1) * (res * res));
        #pragma unroll
        for (int p = 0; p < 4; p++) {
            const int oy = (p >> 1) & 1, oz = p & 1;
            i0[p] = tx[0] + ty[oy] + tz[oz];
            i1[p] = tx[1] + ty[oy] + tz[oz];
        }
    } else {
        u32 ux = (u32)cx, uy = (u32)cy, uz = (u32)cz;
        tx[0] = ux;               tx[1] = ux + 1u;
        ty[0] = uy * 2654435761u; ty[1] = ty[0] + 2654435761u;
        tz[0] = uz * 805459861u;  tz[1] = tz[0] + 805459861u;
        #pragma unroll
        for (int p = 0; p < 4; p++) {
            const int oy = (p >> 1) & 1, oz = p & 1;
            u32 s = ty[oy] ^ tz[oz];
            i0[p] = (tx[0] ^ s) & (TSZ - 1u);
            i1[p] = (tx[1] ^ s) & (TSZ - 1u);
        }
    }
}

// Trilinear reduce from 4 pair-loads (q = float4 covering aligned pair of i0)
// + 4 fallback float2 loads (e, valid when pair not merged).
__device__ __forceinline__ u32 pair_reduce(const float4 q[4], const float2 e[4],
                                           const u32 i0[4], const u32 i1[4],
                                           const float w[3])
{
    const float wx = w[0], wy = w[1], wz = w[2];
    const float wx0 = 1.f - wx, wy0 = 1.f - wy, wz0 = 1.f - wz;
    float f0 = 0.f, f1 = 0.f;
    #pragma unroll
    for (int p = 0; p < 4; p++) {
        const int oy = (p >> 1) & 1, oz = p & 1;
        const bool hi = (i0[p] & 1u) != 0u;
        float2 c0 = hi ? make_float2(q[p].z, q[p].w) : make_float2(q[p].x, q[p].y);
        float2 ot = hi ? make_float2(q[p].x, q[p].y) : make_float2(q[p].z, q[p].w);
        float2 c1 = ((i0[p] ^ i1[p]) == 1u) ? ot : e[p];
        float wyz = (oy ? wy : wy0) * (oz ? wz : wz0);
        float w0 = wx0 * wyz, w1 = wx * wyz;
        f0 = fmaf(w0, c0.x, fmaf(w1, c1.x, f0));
        f1 = fmaf(w0, c0.y, fmaf(w1, c1.y, f1));
    }
    return f22h2(f1, f0);
}

__global__ void __launch_bounds__(BLOCK, 2)
sdf_kernel(const float* __restrict__ x,
           const float* __restrict__ table,
           const float* __restrict__ w1,
           const float* __restrict__ w2,
           const float* __restrict__ w3,
           const float* __restrict__ w4,
           float* __restrict__ out,
           int n, LvlParams P)
{
    __shared__ __align__(16) __half s_w1[64 * 40];
    __shared__ __align__(16) __half s_w2[64 * 72];
    __shared__ __align__(16) __half s_w3[64 * 72];
    __shared__ float s_w4[64];
    __shared__ __align__(16) __half s_enc[BLOCK * 40]; // row stride 40 halves (80B)

    const int tid  = threadIdx.x;
    const int lane = tid & 31;
    const int warp = tid >> 5;

    // ---- prologue: convert weights to fp16 smem ----
    for (int t = tid; t < 64 * 32; t += BLOCK) {
        int nn = t >> 5, kk = t & 31;
        s_w1[nn * 40 + kk] = __float2half_rn(w1[t]);
    }
    for (int t = tid; t < 64 * 64; t += BLOCK) {
        int nn = t >> 6, kk = t & 63;
        s_w2[nn * 72 + kk] = __float2half_rn(w2[t]);
        s_w3[nn * 72 + kk] = __float2half_rn(w3[t]);
    }
    if (tid < 64) s_w4[tid] = w4[tid];
    __syncthreads();

    // ---- encode: level pairs, paired-corner float4 gathers ----
    const int i  = blockIdx.x * BLOCK + tid;
    const int ic = (i < n) ? i : (n - 1);
    const float px = x[3 * ic + 0];
    const float py = x[3 * ic + 1];
    const float pz = x[3 * ic + 2];

    u32* encw = reinterpret_cast<u32*>(s_enc);

    #pragma unroll 1
    for (int lp = 0; lp < NLV / 2; lp++) {
        const int lA = 2 * lp, lB = 2 * lp + 1;
        u32 i0A[4], i1A[4], i0B[4], i1B[4];
        float wA[3], wB[3];
        pair_setup(px, py, pz, P.scale[lA], P.res[lA], P.dense[lA] != 0, i0A, i1A, wA);
        pair_setup(px, py, pz, P.scale[lB], P.res[lB], P.dense[lB] != 0, i0B, i1B, wB);

        const float2* tA = reinterpret_cast<const float2*>(table) + (size_t)lA * TSZ;
        const float2* tB = reinterpret_cast<const float2*>(table) + (size_t)lB * TSZ;
        const float4* t4A = reinterpret_cast<const float4*>(tA);
        const float4* t4B = reinterpret_cast<const float4*>(tB);

        // primary pair loads: full-warp LDG.128
        float4 qA[4], qB[4];
        #pragma unroll
        for (int p = 0; p < 4; p++) qA[p] = __ldg(&t4A[i0A[p] >> 1]);
        #pragma unroll
        for (int p = 0; p < 4; p++) qB[p] = __ldg(&t4B[i0B[p] >> 1]);

        // fallback loads: predicated, only unmerged lanes
        float2 eA[4], eB[4];
        #pragma unroll
        for (int p = 0; p < 4; p++) {
            eA[p] = make_float2(0.f, 0.f);
            if ((i0A[p] ^ i1A[p]) != 1u) eA[p] = __ldg(&tA[i1A[p]]);
        }
        #pragma unroll
        for (int p = 0; p < 4; p++) {
            eB[p] = make_float2(0.f, 0.f);
            if ((i0B[p] ^ i1B[p]) != 1u) eB[p] = __ldg(&tB[i1B[p]]);
        }

        encw[tid * 20 + lA] = pair_reduce(qA, eA, i0A, i1A, wA);
        encw[tid * 20 + lB] = pair_reduce(qB, eB, i0B, i1B, wB);
    }
    __syncwarp();  // enc rows are warp-private

    // ---- MLP on tensor cores (verbatim round-5) ----
    const u32 enc_b = (u32)__cvta_generic_to_shared(s_enc);
    const u32 w1_b  = (u32)__cvta_generic_to_shared(s_w1);
    const u32 w2_b  = (u32)__cvta_generic_to_shared(s_w2);
    const u32 w3_b  = (u32)__cvta_generic_to_shared(s_w3);

    float d[2][8][4];
    u32   a[2][4][4];

    // layer 1: 32 -> 64
    #pragma unroll
    for (int mt = 0; mt < 2; mt++)
        #pragma unroll
        for (int kt = 0; kt < 2; kt++) {
            u32 addr = enc_b + (u32)((warp * 32 + mt * 16 + (lane & 15)) * 80
                                     + kt * 32 + (lane >> 4) * 16);
            ldsm4(a[mt][kt][0], a[mt][kt][1], a[mt][kt][2], a[mt][kt][3], addr);
        }
    #pragma unroll
    for (int mt = 0; mt < 2; mt++)
        #pragma unroll
        for (int nt = 0; nt < 8; nt++)
            #pragma unroll
            for (int v = 0; v < 4; v++) d[mt][nt][v] = 0.f;

    #pragma unroll
    for (int kt = 0; kt < 2; kt++)
        #pragma unroll
        for (int u = 0; u < 4; u++) {
            u32 b0, b1, b2, b3;
            u32 addr = w1_b + (u32)((u * 16 + (lane >> 4) * 8 + (lane & 7)) * 80
                                    + kt * 32 + ((lane >> 3) & 1) * 16);
            ldsm4(b0, b1, b2, b3, addr);
            #pragma unroll
            for (int mt = 0; mt < 2; mt++) {
                mma16816(d[mt][2 * u],     a[mt][kt], b0, b1);
                mma16816(d[mt][2 * u + 1], a[mt][kt], b2, b3);
            }
        }

    #pragma unroll
    for (int mt = 0; mt < 2; mt++)
        #pragma unroll
        for (int kk = 0; kk < 4; kk++) {
            a[mt][kk][0] = f22h2(softplus10(d[mt][2*kk][1]),   softplus10(d[mt][2*kk][0]));
            a[mt][kk][1] = f22h2(softplus10(d[mt][2*kk][3]),   softplus10(d[mt][2*kk][2]));
            a[mt][kk][2] = f22h2(softplus10(d[mt][2*kk+1][1]), softplus10(d[mt][2*kk+1][0]));
            a[mt][kk][3] = f22h2(softplus10(d[mt][2*kk+1][3]), softplus10(d[mt][2*kk+1][2]));
        }

    // layers 2 and 3: 64 -> 64
    #pragma unroll 1
    for (int layer = 0; layer < 2; layer++) {
        const u32 wb = (layer == 0) ? w2_b : w3_b;
        #pragma unroll
        for (int mt = 0; mt < 2; mt++)
            #pragma unroll
            for (int nt = 0; nt < 8; nt++)
                #pragma unroll
                for (int v = 0; v < 4; v++) d[mt][nt][v] = 0.f;

        #pragma unroll
        for (int kt = 0; kt < 4; kt++)
            #pragma unroll
            for (int u = 0; u < 4; u++) {
                u32 b0, b1, b2, b3;
                u32 addr = wb + (u32)((u * 16 + (lane >> 4) * 8 + (lane & 7)) * 144
                                      + kt * 32 + ((lane >> 3) & 1) * 16);
                ldsm4(b0, b1, b2, b3, addr);
                #pragma unroll
                for (int mt = 0; mt < 2; mt++) {
                    mma16816(d[mt][2 * u],     a[mt][kt], b0, b1);
                    mma16816(d[mt][2 * u + 1], a[mt][kt], b2, b3);
                }
            }

        if (layer == 0) {
            #pragma unroll
            for (int mt = 0; mt < 2; mt++)
                #pragma unroll
                for (int kk = 0; kk < 4; kk++) {
                    a[mt][kk][0] = f22h2(softplus10(d[mt][2*kk][1]),   softplus10(d[mt][2*kk][0]));
                    a[mt][kk][1] = f22h2(softplus10(d[mt][2*kk][3]),   softplus10(d[mt][2*kk][2]));
                    a[mt][kk][2] = f22h2(softplus10(d[mt][2*kk+1][1]), softplus10(d[mt][2*kk+1][0]));
                    a[mt][kk][3] = f22h2(softplus10(d[mt][2*kk+1][3]), softplus10(d[mt][2*kk+1][2]));
                }
        }
    }

    // layer 4: 64 -> 1
    #pragma unroll
    for (int mt = 0; mt < 2; mt++) {
        float p0 = 0.f, p1 = 0.f;
        #pragma unroll
        for (int nt = 0; nt < 8; nt++) {
            int c = nt * 8 + 2 * (lane & 3);
            float wv0 = s_w4[c], wv1 = s_w4[c + 1];
            p0 = fmaf(softplus10(d[mt][nt][0]), wv0, p0);
            p0 = fmaf(softplus10(d[mt][nt][1]), wv1, p0);
            p1 = fmaf(softplus10(d[mt][nt][2]), wv0, p1);
            p1 = fmaf(softplus10(d[mt][nt][3]), wv1, p1);
        }
        p0 += __shfl_xor_sync(0xffffffffu, p0, 1);
        p0 += __shfl_xor_sync(0xffffffffu, p0, 2);
        p1 += __shfl_xor_sync(0xffffffffu, p1, 1);
        p1 += __shfl_xor_sync(0xffffffffu, p1, 2);
        if ((lane & 3) == 0) {
            int r0 = blockIdx.x * BLOCK + warp * 32 + mt * 16 + (lane >> 2);
            if (r0 < n) out[r0] = p0;
            int r1 = r0 + 8;
            if (r1 < n) out[r1] = p1;
        }
    }
}

extern "C" void kernel_launch(void* const* d_in, const int* in_sizes, int n_in,
                              void* d_out, int out_size)
{
    const float* x     = (const float*)d_in[0];
    const float* table = (const float*)d_in[1];
    const float* w1    = (const float*)d_in[2];
    const float* w2    = (const float*)d_in[3];
    const float* w3    = (const float*)d_in[4];
    const float* w4    = (const float*)d_in[5];
    float* out = (float*)d_out;

    const int n = in_sizes[0] / 3;

    LvlParams P;
    const double pls = exp2(7.0 / 15.0);
    const double l2s = log2(pls);
    for (int l = 0; l < NLV; l++) {
        double s = exp2((double)l * l2s) * 16.0 - 1.0;
        P.scale[l] = (float)s;
        long long r = (long long)ceil(s) + 1;
        P.res[l] = (int)r;
        P.dense[l] = (r * r * r <= (long long)TSZ) ? 1 : 0;
    }

    int grid = (n + BLOCK - 1) / BLOCK;
    sdf_kernel<<<grid, BLOCK>>>(x, table, w1, w2, w3, w4, out, n, P);
}

// round 8
// speedup vs baseline: 1.3149x; 1.1975x over previous
#include <cuda_runtime.h>
#include <cuda_fp16.h>
#include <math.h>
#include <stdint.h>

#define NLV   16
#define TBITS 19
#define TSZ   (1u << TBITS)
#define BLOCK 256

typedef unsigned int u32;

struct LvlParams {
    float scale[NLV];
    int   res[NLV];
    int   dense[NLV];
};

// softplus(10z)/10 = max(z,0) + (ln2/10) * lg2(1 + 2^(-10*log2(e)*|z|))
__device__ __forceinline__ float softplus10(float z) {
    float e, l;
    float a = -14.426950408889634f * fabsf(z);
    asm("ex2.approx.ftz.f32 %0, %1;" : "=f"(e) : "f"(a));
    float p = 1.0f + e;
    asm("lg2.approx.ftz.f32 %0, %1;" : "=f"(l) : "f"(p));
    return fmaf(l, 0.069314718055994531f, fmaxf(z, 0.0f));
}

// pack two f32 -> f16x2; first operand lands in HIGH half
__device__ __forceinline__ u32 f22h2(float hi, float lo) {
    u32 r;
    asm("cvt.rn.f16x2.f32 %0, %1, %2;" : "=r"(r) : "f"(hi), "f"(lo));
    return r;
}

__device__ __forceinline__ void ldsm4(u32& r0, u32& r1, u32& r2, u32& r3, u32 addr) {
    asm volatile("ldmatrix.sync.aligned.m8n8.x4.shared.b16 {%0,%1,%2,%3}, [%4];"
        : "=r"(r0), "=r"(r1), "=r"(r2), "=r"(r3) : "r"(addr));
}

__device__ __forceinline__ void mma16816(float* d, const u32* a, u32 b0, u32 b1) {
    asm volatile("mma.sync.aligned.m16n8k16.row.col.f32.f16.f16.f32 "
        "{%0,%1,%2,%3},{%4,%5,%6,%7},{%8,%9},{%0,%1,%2,%3};"
        : "+f"(d[0]), "+f"(d[1]), "+f"(d[2]), "+f"(d[3])
        : "r"(a[0]), "r"(a[1]), "r"(a[2]), "r"(a[3]), "r"(b0), "r"(b1));
}

// Per level: 4 x-corner index pairs + interp weights (r7-proven).
__device__ __forceinline__ void pair_setup(float px, float py, float pz,
                                           float sc, int res, bool dens,
                                           u32 i0[4], u32 i1[4], float w[3])
{
    float fx = px * sc + 0.5f, fy = py * sc + 0.5f, fz = pz * sc + 0.5f;
    float gx = floorf(fx), gy = floorf(fy), gz = floorf(fz);
    w[0] = fx - gx; w[1] = fy - gy; w[2] = fz - gz;
    int cx = (int)gx, cy = (int)gy, cz = (int)gz;

    u32 tx[2], ty[2], tz[2];
    if (dens) {
        tx[0] = (u32)min(max(cx,     0), res - 1);
        tx[1] = (u32)min(max(cx + 1, 0), res - 1);
        ty[0] = (u32)(min(max(cy,     0), res - 1) * res);
        ty[1] = (u32)(min(max(cy + 1, 0), res - 1) * res);
        tz[0] = (u32)(min(max(cz,     0), res - 1) * (res * res));
        tz[1] = (u32)(min(max(cz + 1, 0), res - 1) * (res * res));
        #pragma unroll
        for (int p = 0; p < 4; p++) {
            const int oy = (p >> 1) & 1, oz = p & 1;
            i0[p] = tx[0] + ty[oy] + tz[oz];
            i1[p] = tx[1] + ty[oy] + tz[oz];
        }
    } else {
        u32 ux = (u32)cx, uy = (u32)cy, uz = (u32)cz;
        tx[0] = ux;               tx[1] = ux + 1u;
        ty[0] = uy * 2654435761u; ty[1] = ty[0] + 2654435761u;
        tz[0] = uz * 805459861u;  tz[1] = tz[0] + 805459861u;
        #pragma unroll
        for (int p = 0; p < 4; p++) {
            const int oy = (p >> 1) & 1, oz = p & 1;
            u32 s = ty[oy] ^ tz[oz];
            i0[p] = (tx[0] ^ s) & (TSZ - 1u);
            i1[p] = (tx[1] ^ s) & (TSZ - 1u);
        }
    }
}

__device__ __forceinline__ u32 pair_reduce(const float4 q[4], const float2 e[4],
                                           const u32 i0[4], const u32 i1[4],
                                           const float w[3])
{
    const float wx = w[0], wy = w[1], wz = w[2];
    const float wx0 = 1.f - wx, wy0 = 1.f - wy, wz0 = 1.f - wz;
    float f0 = 0.f, f1 = 0.f;
    #pragma unroll
    for (int p = 0; p < 4; p++) {
        const int oy = (p >> 1) & 1, oz = p & 1;
        const bool hi = (i0[p] & 1u) != 0u;
        float2 c0 = hi ? make_float2(q[p].z, q[p].w) : make_float2(q[p].x, q[p].y);
        float2 ot = hi ? make_float2(q[p].x, q[p].y) : make_float2(q[p].z, q[p].w);
        float2 c1 = ((i0[p] ^ i1[p]) == 1u) ? ot : e[p];
        float wyz = (oy ? wy : wy0) * (oz ? wz : wz0);
        float w0 = wx0 * wyz, w1 = wx * wyz;
        f0 = fmaf(w0, c0.x, fmaf(w1, c1.x, f0));
        f1 = fmaf(w0, c0.y, fmaf(w1, c1.y, f1));
    }
    return f22h2(f1, f0);
}

__global__ void __launch_bounds__(BLOCK, 3)
sdf_kernel(const float* __restrict__ x,
           const float* __restrict__ table,
           const float* __restrict__ w1,
           const float* __restrict__ w2,
           const float* __restrict__ w3,
           const float* __restrict__ w4,
           float* __restrict__ out,
           int n, LvlParams P)
{
    __shared__ __align__(16) __half s_w1[64 * 40];
    __shared__ __align__(16) __half s_w2[64 * 72];
    __shared__ __align__(16) __half s_w3[64 * 72];
    __shared__ float s_w4[64];
    __shared__ __align__(16) __half s_enc[BLOCK * 40]; // row stride 40 halves (80B)

    const int tid  = threadIdx.x;
    const int lane = tid & 31;
    const int warp = tid >> 5;

    // ---- prologue: convert weights to fp16 smem ----
    for (int t = tid; t < 64 * 32; t += BLOCK) {
        int nn = t >> 5, kk = t & 31;
        s_w1[nn * 40 + kk] = __float2half_rn(w1[t]);
    }
    for (int t = tid; t < 64 * 64; t += BLOCK) {
        int nn = t >> 6, kk = t & 63;
        s_w2[nn * 72 + kk] = __float2half_rn(w2[t]);
        s_w3[nn * 72 + kk] = __float2half_rn(w3[t]);
    }
    if (tid < 64) s_w4[tid] = w4[tid];
    __syncthreads();

    // ---- encode: level pairs, paired-corner float4 gathers (r7-verbatim) ----
    const int i  = blockIdx.x * BLOCK + tid;
    const int ic = (i < n) ? i : (n - 1);
    const float px = x[3 * ic + 0];
    const float py = x[3 * ic + 1];
    const float pz = x[3 * ic + 2];

    u32* encw = reinterpret_cast<u32*>(s_enc);

    #pragma unroll 1
    for (int lp = 0; lp < NLV / 2; lp++) {
        const int lA = 2 * lp, lB = 2 * lp + 1;
        u32 i0A[4], i1A[4], i0B[4], i1B[4];
        float wA[3], wB[3];
        pair_setup(px, py, pz, P.scale[lA], P.res[lA], P.dense[lA] != 0, i0A, i1A, wA);
        pair_setup(px, py, pz, P.scale[lB], P.res[lB], P.dense[lB] != 0, i0B, i1B, wB);

        const float2* tA = reinterpret_cast<const float2*>(table) + (size_t)lA * TSZ;
        const float2* tB = reinterpret_cast<const float2*>(table) + (size_t)lB * TSZ;
        const float4* t4A = reinterpret_cast<const float4*>(tA);
        const float4* t4B = reinterpret_cast<const float4*>(tB);

        float4 qA[4], qB[4];
        #pragma unroll
        for (int p = 0; p < 4; p++) qA[p] = __ldg(&t4A[i0A[p] >> 1]);
        #pragma unroll
        for (int p = 0; p < 4; p++) qB[p] = __ldg(&t4B[i0B[p] >> 1]);

        float2 eA[4], eB[4];
        #pragma unroll
        for (int p = 0; p < 4; p++) {
            eA[p] = make_float2(0.f, 0.f);
            if ((i0A[p] ^ i1A[p]) != 1u) eA[p] = __ldg(&tA[i1A[p]]);
        }
        #pragma unroll
        for (int p = 0; p < 4; p++) {
            eB[p] = make_float2(0.f, 0.f);
            if ((i0B[p] ^ i1B[p]) != 1u) eB[p] = __ldg(&tB[i1B[p]]);
        }

        encw[tid * 20 + lA] = pair_reduce(qA, eA, i0A, i1A, wA);
        encw[tid * 20 + lB] = pair_reduce(qB, eB, i0B, i1B, wB);
    }
    __syncwarp();  // enc rows are warp-private

    // ---- MLP on tensor cores: 32 pts/warp, sequential m-tiles (low-reg) ----
    const u32 enc_b = (u32)__cvta_generic_to_shared(s_enc);
    const u32 w1_b  = (u32)__cvta_generic_to_shared(s_w1);
    const u32 w2_b  = (u32)__cvta_generic_to_shared(s_w2);
    const u32 w3_b  = (u32)__cvta_generic_to_shared(s_w3);

    #pragma unroll 1
    for (int mt = 0; mt < 2; mt++) {
        float d[8][4];
        u32   a[4][4];

        // layer 1: 32 -> 64
        #pragma unroll
        for (int kt = 0; kt < 2; kt++) {
            u32 addr = enc_b + (u32)((warp * 32 + mt * 16 + (lane & 15)) * 80
                                     + kt * 32 + (lane >> 4) * 16);
            ldsm4(a[kt][0], a[kt][1], a[kt][2], a[kt][3], addr);
        }
        #pragma unroll
        for (int nt = 0; nt < 8; nt++)
            #pragma unroll
            for (int v = 0; v < 4; v++) d[nt][v] = 0.f;

        #pragma unroll
        for (int kt = 0; kt < 2; kt++)
            #pragma unroll
            for (int u = 0; u < 4; u++) {
                u32 b0, b1, b2, b3;
                u32 addr = w1_b + (u32)((u * 16 + (lane >> 4) * 8 + (lane & 7)) * 80
                                        + kt * 32 + ((lane >> 3) & 1) * 16);
                ldsm4(b0, b1, b2, b3, addr);
                mma16816(d[2 * u],     a[kt], b0, b1);
                mma16816(d[2 * u + 1], a[kt], b2, b3);
            }

        #pragma unroll
        for (int kk = 0; kk < 4; kk++) {
            a[kk][0] = f22h2(softplus10(d[2*kk][1]),   softplus10(d[2*kk][0]));
            a[kk][1] = f22h2(softplus10(d[2*kk][3]),   softplus10(d[2*kk][2]));
            a[kk][2] = f22h2(softplus10(d[2*kk+1][1]), softplus10(d[2*kk+1][0]));
            a[kk][3] = f22h2(softplus10(d[2*kk+1][3]), softplus10(d[2*kk+1][2]));
        }

        // layers 2 and 3: 64 -> 64
        #pragma unroll 1
        for (int layer = 0; layer < 2; layer++) {
            const u32 wb = (layer == 0) ? w2_b : w3_b;
            #pragma unroll
            for (int nt = 0; nt < 8; nt++)
                #pragma unroll
                for (int v = 0; v < 4; v++) d[nt][v] = 0.f;

            #pragma unroll
            for (int kt = 0; kt < 4; kt++)
                #pragma unroll
                for (int u = 0; u < 4; u++) {
                    u32 b0, b1, b2, b3;
                    u32 addr = wb + (u32)((u * 16 + (lane >> 4) * 8 + (lane & 7)) * 144
                                          + kt * 32 + ((lane >> 3) & 1) * 16);
                    ldsm4(b0, b1, b2, b3, addr);
                    mma16816(d[2 * u],     a[kt], b0, b1);
                    mma16816(d[2 * u + 1], a[kt], b2, b3);
                }

            if (layer == 0) {
                #pragma unroll
                for (int kk = 0; kk < 4; kk++) {
                    a[kk][0] = f22h2(softplus10(d[2*kk][1]),   softplus10(d[2*kk][0]));
                    a[kk][1] = f22h2(softplus10(d[2*kk][3]),   softplus10(d[2*kk][2]));
                    a[kk][2] = f22h2(softplus10(d[2*kk+1][1]), softplus10(d[2*kk+1][0]));
                    a[kk][3] = f22h2(softplus10(d[2*kk+1][3]), softplus10(d[2*kk+1][2]));
                }
            }
        }

        // layer 4: 64 -> 1
        {
            float p0 = 0.f, p1 = 0.f;
            #pragma unroll
            for (int nt = 0; nt < 8; nt++) {
                int c = nt * 8 + 2 * (lane & 3);
                float wv0 = s_w4[c], wv1 = s_w4[c + 1];
                p0 = fmaf(softplus10(d[nt][0]), wv0, p0);
                p0 = fmaf(softplus10(d[nt][1]), wv1, p0);
                p1 = fmaf(softplus10(d[nt][2]), wv0, p1);
                p1 = fmaf(softplus10(d[nt][3]), wv1, p1);
            }
            p0 += __shfl_xor_sync(0xffffffffu, p0, 1);
            p0 += __shfl_xor_sync(0xffffffffu, p0, 2);
            p1 += __shfl_xor_sync(0xffffffffu, p1, 1);
            p1 += __shfl_xor_sync(0xffffffffu, p1, 2);
            if ((lane & 3) == 0) {
                int r0 = blockIdx.x * BLOCK + warp * 32 + mt * 16 + (lane >> 2);
                if (r0 < n) out[r0] = p0;
                int r1 = r0 + 8;
                if (r1 < n) out[r1] = p1;
            }
        }
    }
}

extern "C" void kernel_launch(void* const* d_in, const int* in_sizes, int n_in,
                              void* d_out, int out_size)
{
    const float* x     = (const float*)d_in[0];
    const float* table = (const float*)d_in[1];
    const float* w1    = (const float*)d_in[2];
    const float* w2    = (const float*)d_in[3];
    const float* w3    = (const float*)d_in[4];
    const float* w4    = (const float*)d_in[5];
    float* out = (float*)d_out;

    const int n = in_sizes[0] / 3;

    LvlParams P;
    const double pls = exp2(7.0 / 15.0);
    const double l2s = log2(pls);
    for (int l = 0; l < NLV; l++) {
        double s = exp2((double)l * l2s) * 16.0 - 1.0;
        P.scale[l] = (float)s;
        long long r = (long long)ceil(s) + 1;
        P.res[l] = (int)r;
        P.dense[l] = (r * r * r <= (long long)TSZ) ? 1 : 0;
    }

    int grid = (n + BLOCK - 1) / BLOCK;
    sdf_kernel<<<grid, BLOCK>>>(x, table, w1, w2, w3, w4, out, n, P);
}